// round 4
// baseline (speedup 1.0000x reference)
#include <cuda_runtime.h>
#include <cuda_bf16.h>
#include <stdint.h>

// Inputs (metadata order):
//   d_in[0]: inputs_t  int32  [1, n_source]   (n_source = 17400)
//   d_in[1]: indices   int32  [N_SYN, 2]  -> (post, pre) per row
//   d_in[2]: weights   float32 [N_SYN]
//   d_in[3]: n_post    (scalar; we use out_size instead)
// Output: float32 [1, n_post]

// Bitmask of active sources, built per call (deterministic, no caching).
// Sized for up to 2M sources (64K words = 256KB) — far above n_source=17400.
__device__ uint32_t g_actbits[65536];

// Prep kernel: zero the output AND build the activity bitmask in one launch.
__global__ void __launch_bounds__(256) prep_kernel(
    const int* __restrict__ act, int n_source,
    float* __restrict__ out, int n_out,
    int n_src_padded)   // n_source rounded up to multiple of 32
{
    int i = blockIdx.x * blockDim.x + threadIdx.x;

    if (i < n_out) out[i] = 0.0f;

    if (i < n_src_padded) {
        bool active = (i < n_source) && (act[i] > 0);
        unsigned mask = __ballot_sync(0xFFFFFFFFu, active);
        if ((threadIdx.x & 31) == 0) g_actbits[i >> 5] = mask;
    }
}

// 8 synapses per thread: 4x int4 index loads + 2x float4 weight loads,
// activity tested against a shared-memory bitmask (2.2KB), atomics predicated.
__global__ void __launch_bounds__(256) scatter8_kernel(
    const int4*   __restrict__ idx4,   // (post,pre) pairs, 2 per int4
    const float4* __restrict__ w4,
    float*        __restrict__ out,
    int n_oct,                          // n_syn / 8
    int n_words)                        // ceil(n_source/32)
{
    extern __shared__ uint32_t sbits[];
    for (int j = threadIdx.x; j < n_words; j += blockDim.x)
        sbits[j] = g_actbits[j];
    __syncthreads();

    int i = blockIdx.x * blockDim.x + threadIdx.x;
    if (i >= n_oct) return;

    // Front-batched loads for MLP.
    int4   a0 = idx4[4 * i + 0];
    int4   a1 = idx4[4 * i + 1];
    int4   a2 = idx4[4 * i + 2];
    int4   a3 = idx4[4 * i + 3];
    float4 w0 = w4[2 * i + 0];
    float4 w1 = w4[2 * i + 1];

    #define ACTIVE(p) ((sbits[(unsigned)(p) >> 5] >> ((unsigned)(p) & 31u)) & 1u)

    if (ACTIVE(a0.y)) atomicAdd(out + a0.x, w0.x);
    if (ACTIVE(a0.w)) atomicAdd(out + a0.z, w0.y);
    if (ACTIVE(a1.y)) atomicAdd(out + a1.x, w0.z);
    if (ACTIVE(a1.w)) atomicAdd(out + a1.z, w0.w);
    if (ACTIVE(a2.y)) atomicAdd(out + a2.x, w1.x);
    if (ACTIVE(a2.w)) atomicAdd(out + a2.z, w1.y);
    if (ACTIVE(a3.y)) atomicAdd(out + a3.x, w1.z);
    if (ACTIVE(a3.w)) atomicAdd(out + a3.z, w1.w);

    #undef ACTIVE
}

// Tail for n_syn not divisible by 8 (not hit for N_SYN=30M, kept for safety).
__global__ void scatter_tail_kernel(
    const int2* __restrict__ idx2,
    const float* __restrict__ w,
    float*       __restrict__ out,
    int start, int n_syn)
{
    int i = start + blockIdx.x * blockDim.x + threadIdx.x;
    if (i >= n_syn) return;
    int2 p = idx2[i];
    if ((g_actbits[(unsigned)p.y >> 5] >> ((unsigned)p.y & 31u)) & 1u)
        atomicAdd(out + p.x, w[i]);
}

extern "C" void kernel_launch(void* const* d_in, const int* in_sizes, int n_in,
                              void* d_out, int out_size) {
    const int*   act     = (const int*)d_in[0];
    const int*   indices = (const int*)d_in[1];
    const float* weights = (const float*)d_in[2];
    float*       out     = (float*)d_out;

    const int n_source = in_sizes[0];
    const int n_syn    = in_sizes[2];

    const int n_src_padded = (n_source + 31) & ~31;
    const int n_words      = n_src_padded >> 5;

    // Prep: zero output + build bitmask (one launch).
    {
        int span    = out_size > n_src_padded ? out_size : n_src_padded;
        int threads = 256;
        int blocks  = (span + threads - 1) / threads;
        prep_kernel<<<blocks, threads>>>(act, n_source, out, out_size, n_src_padded);
    }

    const int n_oct = n_syn / 8;
    if (n_oct > 0) {
        int threads = 256;
        int blocks  = (n_oct + threads - 1) / threads;
        size_t smem = (size_t)n_words * sizeof(uint32_t);
        scatter8_kernel<<<blocks, threads, smem>>>(
            (const int4*)indices, (const float4*)weights, out, n_oct, n_words);
    }

    const int done = n_oct * 8;
    if (done < n_syn) {
        int rem = n_syn - done;
        int threads = 256;
        int blocks  = (rem + threads - 1) / threads;
        scatter_tail_kernel<<<blocks, threads>>>(
            (const int2*)indices, weights, out, done, n_syn);
    }
}